// round 1
// baseline (speedup 1.0000x reference)
#include <cuda_runtime.h>
#include <math.h>

#define T_STEPS 1024
#define NB 128
#define FD 128
#define HD 128

// Scratch: 8 precomputed floats per (b,t):
//  [0:4) = x_t @ W_in_x^T + b_in   (x-part of y)
//  [4:8) = vqc(x_t @ W_x^T + b_x, vqc_w[2])  (fully h-independent)
__device__ float g_xpre[NB * T_STEPS * 8];

__device__ __forceinline__ float fsig(float x) {
    return __fdividef(1.0f, 1.0f + __expf(-x));
}
__device__ __forceinline__ float ftanhf(float x) {
    x = fminf(fmaxf(x, -30.0f), 30.0f);
    float e = __expf(-2.0f * x);
    return __fdividef(1.0f - e, 1.0f + e);
}

// ---------------------------------------------------------------------------
// Pre-pass: one warp per (b,t) row, grid-stride. Memory bound (~64MB read).
// ---------------------------------------------------------------------------
__global__ void __launch_bounds__(256) qgru_prepass(
    const float* __restrict__ x,
    const float* __restrict__ W_in, const float* __restrict__ b_in,
    const float* __restrict__ W_x,  const float* __restrict__ b_x,
    const float* __restrict__ vqc_w)
{
    const int lane = threadIdx.x & 31;
    const int gw   = (blockIdx.x * blockDim.x + threadIdx.x) >> 5;
    const int nw   = (gridDim.x * blockDim.x) >> 5;

    // per-lane weight slices: dot k over features [4*lane, 4*lane+4)
    float wt[8][4];
#pragma unroll
    for (int k = 0; k < 4; k++) {
#pragma unroll
        for (int i = 0; i < 4; i++) {
            wt[k][i]     = W_in[k * (HD + FD) + HD + lane * 4 + i]; // x-cols of W_in
            wt[4 + k][i] = W_x[k * FD + lane * 4 + i];
        }
    }
    float bi[8], w2[4];
#pragma unroll
    for (int k = 0; k < 4; k++) {
        bi[k]     = b_in[k];
        bi[4 + k] = b_x[k];
        w2[k]     = vqc_w[2 * 4 + k]; // vqc_w[2][0][k]
    }

    const int NROWS = NB * T_STEPS;
    for (int row = gw; row < NROWS; row += nw) {
        float4 xv = *reinterpret_cast<const float4*>(x + (size_t)row * FD + lane * 4);
        float s[8];
#pragma unroll
        for (int k = 0; k < 8; k++) {
            s[k] = wt[k][0] * xv.x;
            s[k] = fmaf(wt[k][1], xv.y, s[k]);
            s[k] = fmaf(wt[k][2], xv.z, s[k]);
            s[k] = fmaf(wt[k][3], xv.w, s[k]);
        }
#pragma unroll
        for (int off = 16; off; off >>= 1) {
#pragma unroll
            for (int k = 0; k < 8; k++)
                s[k] += __shfl_xor_sync(0xffffffffu, s[k], off);
        }
        if (lane == 0) {
            // closed-form VQC for the x-gate (weights row 2)
            float c0 = __cosf(s[4] + bi[4] + w2[0]);
            float c1 = __cosf(s[5] + bi[5] + w2[1]);
            float c2 = __cosf(s[6] + bi[6] + w2[2]);
            float c3 = __cosf(s[7] + bi[7] + w2[3]);
            float z1 = c0 * c1;
            float z2 = z1 * c2;
            float4 o0 = make_float4(s[0] + bi[0], s[1] + bi[1],
                                    s[2] + bi[2], s[3] + bi[3]);
            float4 o1 = make_float4(c1 * c2 * c3, z1, z2, z2 * c3);
            float4* op = reinterpret_cast<float4*>(g_xpre + (size_t)row * 8);
            op[0] = o0;
            op[1] = o1;
        }
    }
}

// ---------------------------------------------------------------------------
// Sequential recurrence: 1 CTA per batch row, 128 threads (thread j owns h_j).
// One __syncthreads per step (double-buffered h in smem; butterfly reduction
// computed redundantly in every warp so no smem round-trip for the dots).
// ---------------------------------------------------------------------------
__global__ void __launch_bounds__(128, 1) qgru_seq(
    const float* __restrict__ W_in, const float* __restrict__ W_h,
    const float* __restrict__ b_h,
    const float* __restrict__ W_out, const float* __restrict__ b_out,
    const float* __restrict__ vqc_w,
    float* __restrict__ out)
{
    const int b    = blockIdx.x;
    const int j    = threadIdx.x;
    const int lane = j & 31;

    __shared__ float h_sh[2][HD];

    // dot weights: s[k] (k<4) = h . W_in[k, 0:H]; s[4+k] = h . W_h[k, :]
    float wreg[8][4];
#pragma unroll
    for (int k = 0; k < 4; k++) {
#pragma unroll
        for (int i = 0; i < 4; i++) {
            wreg[k][i]     = W_in[k * (HD + FD) + lane + 32 * i];
            wreg[4 + k][i] = W_h[k * HD + lane + 32 * i];
        }
    }
    float wo[4];
#pragma unroll
    for (int k = 0; k < 4; k++) wo[k] = W_out[j * 4 + k];
    const float bo = b_out[j];

    float w0[4], w1[4], w3[4], bh[4];
#pragma unroll
    for (int k = 0; k < 4; k++) {
        w0[k] = vqc_w[k];
        w1[k] = vqc_w[4 + k];
        w3[k] = vqc_w[12 + k];
        bh[k] = b_h[k];
    }

    float hj = 0.0f;
    h_sh[0][j] = 0.0f;

    // c_last = zeros
    out[(size_t)NB * T_STEPS * HD + (size_t)NB * HD + b * HD + j] = 0.0f;

    const float4* __restrict__ xp =
        reinterpret_cast<const float4*>(g_xpre + (size_t)b * T_STEPS * 8);
    float4 p0 = xp[0], p1 = xp[1];

    float* __restrict__ orow = out + (size_t)b * T_STEPS * HD + j;

    __syncthreads();

#pragma unroll 1
    for (int t = 0; t < T_STEPS; t++) {
        const float* hb = h_sh[t & 1];
        float hv[4];
#pragma unroll
        for (int i = 0; i < 4; i++) hv[i] = hb[lane + 32 * i];

        float s[8];
#pragma unroll
        for (int k = 0; k < 8; k++) {
            s[k] = hv[0] * wreg[k][0];
            s[k] = fmaf(hv[1], wreg[k][1], s[k]);
            s[k] = fmaf(hv[2], wreg[k][2], s[k]);
            s[k] = fmaf(hv[3], wreg[k][3], s[k]);
        }
#pragma unroll
        for (int off = 16; off; off >>= 1) {
#pragma unroll
            for (int k = 0; k < 8; k++)
                s[k] += __shfl_xor_sync(0xffffffffu, s[k], off);
        }

        // prefetch next step's precomputed values (uniform broadcast load)
        const int tn = (t + 1 < T_STEPS) ? (t + 1) : (T_STEPS - 1);
        float4 np0 = xp[2 * tn];
        float4 np1 = xp[2 * tn + 1];

        float y0 = s[0] + p0.x, y1 = s[1] + p0.y, y2 = s[2] + p0.z, y3 = s[3] + p0.w;
        float q0 = s[4] + bh[0], q1 = s[5] + bh[1], q2 = s[6] + bh[2], q3 = s[7] + bh[3];

        float cr0 = __cosf(y0 + w0[0]), cr1 = __cosf(y1 + w0[1]);
        float cr2 = __cosf(y2 + w0[2]), cr3 = __cosf(y3 + w0[3]);
        float cz0 = __cosf(y0 + w1[0]), cz1 = __cosf(y1 + w1[1]);
        float cz2 = __cosf(y2 + w1[2]), cz3 = __cosf(y3 + w1[3]);
        float ch0 = __cosf(q0 + w3[0]), ch1 = __cosf(q1 + w3[1]);
        float ch2 = __cosf(q2 + w3[2]), ch3 = __cosf(q3 + w3[3]);

        // z-expectations after CNOT ring: (C1C2C3, C0C1, C0C1C2, C0C1C2C3)
        float rA = cr0 * cr1, rB = rA * cr2;
        float o_r = fmaf(cr1 * cr2 * cr3, wo[0],
                    fmaf(rA, wo[1], fmaf(rB, wo[2], fmaf(rB * cr3, wo[3], bo))));
        float zA = cz0 * cz1, zB = zA * cz2;
        float o_z = fmaf(cz1 * cz2 * cz3, wo[0],
                    fmaf(zA, wo[1], fmaf(zB, wo[2], fmaf(zB * cz3, wo[3], bo))));
        float hA = ch0 * ch1, hB = hA * ch2;
        float o_h = fmaf(ch1 * ch2 * ch3, wo[0],
                    fmaf(hA, wo[1], fmaf(hB, wo[2], fmaf(hB * ch3, wo[3], bo))));
        float o_x = fmaf(p1.x, wo[0],
                    fmaf(p1.y, wo[1], fmaf(p1.z, wo[2], fmaf(p1.w, wo[3], bo))));

        float r = fsig(o_r);
        float z = fsig(o_z);
        float n = ftanhf(fmaf(r, o_h, o_x));

        hj = fmaf(z, hj - n, n);          // (1-z)*n + z*h

        orow[(size_t)t * HD] = hj;        // hidden_seq[b, t, j]
        h_sh[(t + 1) & 1][j] = hj;        // publish to other lanes

        __syncthreads();
        p0 = np0; p1 = np1;
    }

    // h_last
    out[(size_t)NB * T_STEPS * HD + b * HD + j] = hj;
}

extern "C" void kernel_launch(void* const* d_in, const int* in_sizes, int n_in,
                              void* d_out, int out_size) {
    const float* x     = (const float*)d_in[0];
    const float* W_in  = (const float*)d_in[1];
    const float* b_in  = (const float*)d_in[2];
    const float* W_x   = (const float*)d_in[3];
    const float* b_x   = (const float*)d_in[4];
    const float* W_h   = (const float*)d_in[5];
    const float* b_h   = (const float*)d_in[6];
    const float* W_out = (const float*)d_in[7];
    const float* b_out = (const float*)d_in[8];
    const float* vqcw  = (const float*)d_in[9];
    float* out = (float*)d_out;

    qgru_prepass<<<592, 256>>>(x, W_in, b_in, W_x, b_x, vqcw);
    qgru_seq<<<NB, HD>>>(W_in, W_h, b_h, W_out, b_out, vqcw, out);
}

// round 3
// speedup vs baseline: 1.0564x; 1.0564x over previous
#include <cuda_runtime.h>
#include <math.h>

#define T_STEPS 1024
#define NB 128
#define FD 128
#define HD 128

// Scratch: 8 precomputed floats per (b,t):
//  [0:4) = x_t @ W_in_x^T + b_in   (x-part of y)
//  [4:8) = vqc(x_t @ W_x^T + b_x, vqc_w[2])  (fully h-independent)
__device__ float g_xpre[NB * T_STEPS * 8];

typedef unsigned long long u64;

__device__ __forceinline__ u64 pack2(float lo, float hi) {
    u64 r;
    asm("mov.b64 %0, {%1, %2};" : "=l"(r) : "f"(lo), "f"(hi));
    return r;
}
__device__ __forceinline__ void unpack2(u64 v, float& lo, float& hi) {
    asm("mov.b64 {%0, %1}, %2;" : "=f"(lo), "=f"(hi) : "l"(v));
}
// Blackwell packed fp32 pair ops (SASS FFMA2 / FADD-pair)
__device__ __forceinline__ u64 fma2(u64 a, u64 b, u64 c) {
    u64 r;
    asm("fma.rn.f32x2 %0, %1, %2, %3;" : "=l"(r) : "l"(a), "l"(b), "l"(c));
    return r;
}
__device__ __forceinline__ u64 add2(u64 a, u64 b) {
    u64 r;
    asm("add.rn.f32x2 %0, %1, %2;" : "=l"(r) : "l"(a), "l"(b));
    return r;
}

__device__ __forceinline__ float fsig(float x) {
    return __fdividef(1.0f, 1.0f + __expf(-x));
}
__device__ __forceinline__ float ftanhf(float x) {
    float e = __expf(-2.0f * x);
    return __fdividef(1.0f - e, 1.0f + e);
}

// ---------------------------------------------------------------------------
// Pre-pass: one warp per (b,t) row, grid-stride. Memory bound (~64MB read).
// ---------------------------------------------------------------------------
__global__ void __launch_bounds__(256) qgru_prepass(
    const float* __restrict__ x,
    const float* __restrict__ W_in, const float* __restrict__ b_in,
    const float* __restrict__ W_x,  const float* __restrict__ b_x,
    const float* __restrict__ vqc_w)
{
    const int lane = threadIdx.x & 31;
    const int gw   = (blockIdx.x * blockDim.x + threadIdx.x) >> 5;
    const int nw   = (gridDim.x * blockDim.x) >> 5;

    float wt[8][4];
#pragma unroll
    for (int k = 0; k < 4; k++) {
#pragma unroll
        for (int i = 0; i < 4; i++) {
            wt[k][i]     = W_in[k * (HD + FD) + HD + lane * 4 + i]; // x-cols of W_in
            wt[4 + k][i] = W_x[k * FD + lane * 4 + i];
        }
    }
    float bi[8], w2[4];
#pragma unroll
    for (int k = 0; k < 4; k++) {
        bi[k]     = b_in[k];
        bi[4 + k] = b_x[k];
        w2[k]     = vqc_w[2 * 4 + k]; // vqc_w[2][0][k]
    }

    const int NROWS = NB * T_STEPS;
    for (int row = gw; row < NROWS; row += nw) {
        float4 xv = *reinterpret_cast<const float4*>(x + (size_t)row * FD + lane * 4);
        float s[8];
#pragma unroll
        for (int k = 0; k < 8; k++) {
            s[k] = wt[k][0] * xv.x;
            s[k] = fmaf(wt[k][1], xv.y, s[k]);
            s[k] = fmaf(wt[k][2], xv.z, s[k]);
            s[k] = fmaf(wt[k][3], xv.w, s[k]);
        }
#pragma unroll
        for (int off = 16; off; off >>= 1) {
#pragma unroll
            for (int k = 0; k < 8; k++)
                s[k] += __shfl_xor_sync(0xffffffffu, s[k], off);
        }
        if (lane == 0) {
            // closed-form VQC for the x-gate (weights row 2)
            float c0 = __cosf(s[4] + bi[4] + w2[0]);
            float c1 = __cosf(s[5] + bi[5] + w2[1]);
            float c2 = __cosf(s[6] + bi[6] + w2[2]);
            float c3 = __cosf(s[7] + bi[7] + w2[3]);
            float z1 = c0 * c1;
            float z2 = z1 * c2;
            float4 o0 = make_float4(s[0] + bi[0], s[1] + bi[1],
                                    s[2] + bi[2], s[3] + bi[3]);
            float4 o1 = make_float4(c1 * c2 * c3, z1, z2, z2 * c3);
            float4* op = reinterpret_cast<float4*>(g_xpre + (size_t)row * 8);
            op[0] = o0;
            op[1] = o1;
        }
    }
}

// ---------------------------------------------------------------------------
// Sequential recurrence: 1 CTA per batch row, 128 threads (thread j owns
// output column j). Dot products: lane group m=lane>>3 owns sums {2m, 2m+1},
// sub=lane&7 owns h[16*sub .. 16*sub+16). 3-level butterfly instead of 5.
// The 12 cosines (uniform across the CTA) are computed by ONE warp-wide
// MUFU.COS (each lane computes its assigned cosine) and distributed by shfl.
// ---------------------------------------------------------------------------
__global__ void __launch_bounds__(128, 1) qgru_seq(
    const float* __restrict__ W_in, const float* __restrict__ W_h,
    const float* __restrict__ b_h,
    const float* __restrict__ W_out, const float* __restrict__ b_out,
    const float* __restrict__ vqc_w,
    float* __restrict__ out)
{
    const int b    = blockIdx.x;
    const int j    = threadIdx.x;
    const int lane = j & 31;
    const int m    = lane >> 3;   // k-pair group: sums k0=2m, k1=2m+1
    const int sub  = lane & 7;    // h-element slice [16*sub, 16*sub+16)

    __shared__ __align__(16) float h_sh[2][HD];

    // Packed weight rows for this lane's two sums over its 16 h elements.
    // k<4 -> W_in[k, 0:128] (h-part); k>=4 -> W_h[k-4, :]
    const int k0 = 2 * m, k1 = 2 * m + 1;
    const float* r0 = (k0 < 4) ? (W_in + k0 * (HD + FD)) : (W_h + (k0 - 4) * HD);
    const float* r1 = (k1 < 4) ? (W_in + k1 * (HD + FD)) : (W_h + (k1 - 4) * HD);
    u64 wA[8], wB[8];
#pragma unroll
    for (int i = 0; i < 8; i++) {
        wA[i] = pack2(r0[sub * 16 + 2 * i], r0[sub * 16 + 2 * i + 1]);
        wB[i] = pack2(r1[sub * 16 + 2 * i], r1[sub * 16 + 2 * i + 1]);
    }

    float wo[4];
#pragma unroll
    for (int k = 0; k < 4; k++) wo[k] = W_out[j * 4 + k];
    const float bo = b_out[j];

    // Per-lane cosine role: loop-invariant additive constant.
    //  m<2 (y sums): c8=0 -> cr_{2m}: +w0[2m];   c8=1 -> cz_{2m}: +w1[2m]
    //                c8=2 -> cr_{2m+1}: +w0[2m+1]; c8=3 -> cz_{2m+1}: +w1[2m+1]
    //  m>=2 (q sums): c8=0 -> ch_{2(m-2)}: +w3+bh;  c8=2 -> ch_{2(m-2)+1}
    const int c8 = sub;
    float cadd;
    if (m < 2) {
        int kk = 2 * m + ((c8 >> 1) & 1);
        cadd = ((c8 & 1) == 0) ? vqc_w[kk] : vqc_w[4 + kk];
    } else {
        int kk = 2 * (m - 2) + ((c8 >> 1) & 1);
        cadd = vqc_w[12 + kk] + b_h[kk];
    }
    const int  kk_p  = 2 * m + ((c8 >> 1) & 1);   // p0 component for y lanes
    const bool use_p = (m < 2);
    const bool useB  = ((c8 & 2) != 0);           // this lane's cosine uses sum k1

    float hj = 0.0f;
    h_sh[0][j] = 0.0f;

    // c_last = zeros
    out[(size_t)NB * T_STEPS * HD + (size_t)NB * HD + b * HD + j] = 0.0f;

    const float4* __restrict__ xp =
        reinterpret_cast<const float4*>(g_xpre + (size_t)b * T_STEPS * 8);
    float4 p0 = xp[0], p1 = xp[1];

    float* __restrict__ orow = out + (size_t)b * T_STEPS * HD + j;

    __syncthreads();

#pragma unroll 1
    for (int t = 0; t < T_STEPS; t++) {
        const ulonglong2* hp = reinterpret_cast<const ulonglong2*>(
            h_sh[t & 1] + sub * 16);

        u64 a0 = 0ull, a1 = 0ull, b0 = 0ull, b1 = 0ull;
#pragma unroll
        for (int i = 0; i < 4; i++) {
            ulonglong2 hv = hp[i];
            a0 = fma2(hv.x, wA[2 * i],     a0);
            a1 = fma2(hv.y, wA[2 * i + 1], a1);
            b0 = fma2(hv.x, wB[2 * i],     b0);
            b1 = fma2(hv.y, wB[2 * i + 1], b1);
        }
        // prefetch next step's precomputed values (independent of reductions)
        const int tn = (t + 1 < T_STEPS) ? (t + 1) : (T_STEPS - 1);
        float4 np0 = xp[2 * tn];
        float4 np1 = xp[2 * tn + 1];

        a0 = add2(a0, a1);
        b0 = add2(b0, b1);
        float alo, ahi, blo, bhi;
        unpack2(a0, alo, ahi);
        unpack2(b0, blo, bhi);
        float sA = alo + ahi;
        float sB = blo + bhi;

        // 3-level butterfly over sub (lanes within the 8-lane group)
#pragma unroll
        for (int off = 1; off <= 4; off <<= 1) {
            sA += __shfl_xor_sync(0xffffffffu, sA, off);
            sB += __shfl_xor_sync(0xffffffffu, sB, off);
        }

        // one warp-wide cosine computes all 12 gate cosines
        float ssel = useB ? sB : sA;
        float pc = (kk_p == 0) ? p0.x : (kk_p == 1) ? p0.y
                 : (kk_p == 2) ? p0.z : p0.w;
        float arg = ssel + cadd + (use_p ? pc : 0.0f);
        float cv = __cosf(arg);

        float cr0 = __shfl_sync(0xffffffffu, cv, 0);
        float cz0 = __shfl_sync(0xffffffffu, cv, 1);
        float cr1 = __shfl_sync(0xffffffffu, cv, 2);
        float cz1 = __shfl_sync(0xffffffffu, cv, 3);
        float cr2 = __shfl_sync(0xffffffffu, cv, 8);
        float cz2 = __shfl_sync(0xffffffffu, cv, 9);
        float cr3 = __shfl_sync(0xffffffffu, cv, 10);
        float cz3 = __shfl_sync(0xffffffffu, cv, 11);
        float ch0 = __shfl_sync(0xffffffffu, cv, 16);
        float ch1 = __shfl_sync(0xffffffffu, cv, 18);
        float ch2 = __shfl_sync(0xffffffffu, cv, 24);
        float ch3 = __shfl_sync(0xffffffffu, cv, 26);

        // z-expectations after CNOT ring: (C1C2C3, C0C1, C0C1C2, C0C1C2C3)
        float rm = cr1 * cr2;
        float rA = cr0 * cr1, rB = cr0 * rm;
        float o_r = fmaf(rm * cr3, wo[0],
                    fmaf(rA, wo[1], fmaf(rB, wo[2], fmaf(rB * cr3, wo[3], bo))));
        float Er = __expf(-o_r);                 // start r's MUFU chain early

        float hm = ch1 * ch2;
        float hA = ch0 * ch1, hB = ch0 * hm;
        float o_h = fmaf(hm * ch3, wo[0],
                    fmaf(hA, wo[1], fmaf(hB, wo[2], fmaf(hB * ch3, wo[3], bo))));

        float zm = cz1 * cz2;
        float zA = cz0 * cz1, zB = cz0 * zm;
        float o_z = fmaf(zm * cz3, wo[0],
                    fmaf(zA, wo[1], fmaf(zB, wo[2], fmaf(zB * cz3, wo[3], bo))));

        float o_x = fmaf(p1.x, wo[0],
                    fmaf(p1.y, wo[1], fmaf(p1.z, wo[2], fmaf(p1.w, wo[3], bo))));

        float r = __fdividef(1.0f, 1.0f + Er);
        float z = fsig(o_z);
        float n = ftanhf(fmaf(r, o_h, o_x));

        hj = fmaf(z, hj - n, n);          // (1-z)*n + z*h

        h_sh[(t + 1) & 1][j] = hj;        // publish to other lanes
        orow[(size_t)t * HD] = hj;        // hidden_seq[b, t, j]

        __syncthreads();
        p0 = np0; p1 = np1;
    }

    // h_last
    out[(size_t)NB * T_STEPS * HD + b * HD + j] = hj;
}

extern "C" void kernel_launch(void* const* d_in, const int* in_sizes, int n_in,
                              void* d_out, int out_size) {
    const float* x     = (const float*)d_in[0];
    const float* W_in  = (const float*)d_in[1];
    const float* b_in  = (const float*)d_in[2];
    const float* W_x   = (const float*)d_in[3];
    const float* b_x   = (const float*)d_in[4];
    const float* W_h   = (const float*)d_in[5];
    const float* b_h   = (const float*)d_in[6];
    const float* W_out = (const float*)d_in[7];
    const float* b_out = (const float*)d_in[8];
    const float* vqcw  = (const float*)d_in[9];
    float* out = (float*)d_out;

    qgru_prepass<<<592, 256>>>(x, W_in, b_in, W_x, b_x, vqcw);
    qgru_seq<<<NB, HD>>>(W_in, W_h, b_h, W_out, b_out, vqcw, out);
}